// round 7
// baseline (speedup 1.0000x reference)
#include <cuda_runtime.h>
#include <math.h>

#define Bb 16
#define Nn 200
#define Dd 128
#define Hh 8
#define ROWS (Bb*Nn)          // 3200
#define NEG_SLOPE 0.2f
#define RPB 16                // rows per gemm block
#define HS 20                 // hT row stride (floats)

// Scratch (static device globals — no allocation)
__device__ float g_buf[ROWS * Dd];      // g = h @ W           (1.6 MB)
__device__ float si_buf[ROWS * Hh];     // s_i
__device__ float sj_buf[ROWS * Hh];     // s_j
__device__ float c3g[Dd * Hh];          // W_e folded with a3

// ---------------------------------------------------------------------------
// Kernel A: blocks 0..199: g = h @ W (W streamed via L1, hT in 10KB smem),
//           s_i/s_j fused from live accumulators.
//           blocks 200..207: c3[d][h] = sum_q W_e[d,h*16+q]*a3[q].
// ---------------------------------------------------------------------------
__global__ void __launch_bounds__(256) gemm_fused(const float* __restrict__ h,
                                                  const float* __restrict__ W,
                                                  const float* __restrict__ We,
                                                  const float* __restrict__ a)
{
    __shared__ float hT[Dd * HS];        // transposed h tile
    __shared__ float ash[48];

    int t = threadIdx.x;

    if (blockIdx.x >= 200) {             // ---- c3 path (one head per block)
        int hd = blockIdx.x - 200;
        __shared__ float a3sh[16];
        if (t < 16) a3sh[t] = a[32 + t];
        __syncthreads();
        if (t < Dd) {
            const float4* row = (const float4*)(We + (size_t)t * Dd + hd * 16);
            float s = 0.f;
            #pragma unroll
            for (int qv = 0; qv < 4; qv++) {
                float4 w4 = row[qv];
                s += w4.x * a3sh[qv * 4 + 0] + w4.y * a3sh[qv * 4 + 1]
                   + w4.z * a3sh[qv * 4 + 2] + w4.w * a3sh[qv * 4 + 3];
            }
            c3g[t * Hh + hd] = s;
        }
        return;
    }

    int row0 = blockIdx.x * RPB;
    if (t < 32) ash[t] = a[t];

    // Stage h tile transposed: hT[k][r] (coalesced global reads).
    #pragma unroll 2
    for (int idx = t; idx < RPB * Dd; idx += 256) {
        int r = idx >> 7, k = idx & 127;
        hT[k * HS + r] = h[(size_t)(row0 + r) * Dd + k];
    }
    __syncthreads();

    int cvec = t & 31;               // float4 col index (c0 = cvec*4)
    int c0   = cvec * 4;
    int r0   = (t >> 5) * 2;         // 2 rows per thread
    float acc0[4] = {0.f, 0.f, 0.f, 0.f};
    float acc1[4] = {0.f, 0.f, 0.f, 0.f};

    const float4* Wv = (const float4*)W;
    #pragma unroll 8
    for (int k = 0; k < Dd; k++) {
        float4 w4 = Wv[k * 32 + cvec];                     // L1-resident
        float2 h2 = *(const float2*)&hT[k * HS + r0];      // broadcast
        acc0[0] += h2.x * w4.x;  acc0[1] += h2.x * w4.y;
        acc0[2] += h2.x * w4.z;  acc0[3] += h2.x * w4.w;
        acc1[0] += h2.y * w4.x;  acc1[1] += h2.y * w4.y;
        acc1[2] += h2.y * w4.z;  acc1[3] += h2.y * w4.w;
    }
    *(float4*)&g_buf[(size_t)(row0 + r0)     * Dd + c0] =
        make_float4(acc0[0], acc0[1], acc0[2], acc0[3]);
    *(float4*)&g_buf[(size_t)(row0 + r0 + 1) * Dd + c0] =
        make_float4(acc1[0], acc1[1], acc1[2], acc1[3]);

    // Fused s_i/s_j: head = c0>>4; quad (t&3 over 4 cvecs) covers 16 q's.
    {
        int head = c0 >> 4;
        int qb   = c0 & 15;
        const float* a1 = ash;
        const float* a2 = ash + 16;
        float pi0 = acc0[0]*a1[qb] + acc0[1]*a1[qb+1] + acc0[2]*a1[qb+2] + acc0[3]*a1[qb+3];
        float pj0 = acc0[0]*a2[qb] + acc0[1]*a2[qb+1] + acc0[2]*a2[qb+2] + acc0[3]*a2[qb+3];
        float pi1 = acc1[0]*a1[qb] + acc1[1]*a1[qb+1] + acc1[2]*a1[qb+2] + acc1[3]*a1[qb+3];
        float pj1 = acc1[0]*a2[qb] + acc1[1]*a2[qb+1] + acc1[2]*a2[qb+2] + acc1[3]*a2[qb+3];
        pi0 += __shfl_xor_sync(0xffffffffu, pi0, 1);
        pi0 += __shfl_xor_sync(0xffffffffu, pi0, 2);
        pj0 += __shfl_xor_sync(0xffffffffu, pj0, 1);
        pj0 += __shfl_xor_sync(0xffffffffu, pj0, 2);
        pi1 += __shfl_xor_sync(0xffffffffu, pi1, 1);
        pi1 += __shfl_xor_sync(0xffffffffu, pi1, 2);
        pj1 += __shfl_xor_sync(0xffffffffu, pj1, 1);
        pj1 += __shfl_xor_sync(0xffffffffu, pj1, 2);
        if ((t & 3) == 0) {
            si_buf[(row0 + r0)     * Hh + head] = pi0;
            sj_buf[(row0 + r0)     * Hh + head] = pj0;
            si_buf[(row0 + r0 + 1) * Hh + head] = pi1;
            sj_buf[(row0 + r0 + 1) * Hh + head] = pj1;
        }
    }
}

// ---------------------------------------------------------------------------
// process_j: 8-head dot + head-folding butterfly (9 shfl); lane h*4 ends with
// head h's total; lanes (lane&3)==0 finish the logit and store esh2[j][h].
// ---------------------------------------------------------------------------
__device__ __forceinline__ void process_j(float4 dv, int jj, int lane,
                                          const float* c3r,
                                          float4 si0, float4 si1,
                                          const float* sjsh,
                                          const int*   adjsh,
                                          float*       esh2)
{
    float v[8];
    #pragma unroll
    for (int h = 0; h < 8; h++)
        v[h] = dv.x * c3r[h]      + dv.y * c3r[8 + h]
             + dv.z * c3r[16 + h] + dv.w * c3r[24 + h];

    float w4[4];
    {
        bool hi = (lane & 16) != 0;
        #pragma unroll
        for (int k = 0; k < 4; k++) {
            float send = hi ? v[k] : v[k + 4];
            float recv = __shfl_xor_sync(0xffffffffu, send, 16);
            w4[k] = (hi ? v[k + 4] : v[k]) + recv;
        }
    }
    float w2[2];
    {
        bool hi = (lane & 8) != 0;
        #pragma unroll
        for (int k = 0; k < 2; k++) {
            float send = hi ? w4[k] : w4[k + 2];
            float recv = __shfl_xor_sync(0xffffffffu, send, 8);
            w2[k] = (hi ? w4[k + 2] : w4[k]) + recv;
        }
    }
    float y;
    {
        bool hi = (lane & 4) != 0;
        float send = hi ? w2[0] : w2[1];
        float recv = __shfl_xor_sync(0xffffffffu, send, 4);
        y = (hi ? w2[1] : w2[0]) + recv;
    }
    y += __shfl_xor_sync(0xffffffffu, y, 1);
    y += __shfl_xor_sync(0xffffffffu, y, 2);

    if ((lane & 3) == 0) {
        int head = lane >> 2;
        float si = (head < 4) ? ((head == 0) ? si0.x : (head == 1) ? si0.y
                                : (head == 2) ? si0.z : si0.w)
                              : ((head == 4) ? si1.x : (head == 5) ? si1.y
                                : (head == 6) ? si1.z : si1.w);
        float e = si + sjsh[jj * Hh + head] + y;
        e = (e > 0.f) ? e : NEG_SLOPE * e;          // leaky relu
        if (adjsh[jj] == 0) e = -INFINITY;          // mask
        esh2[jj * Hh + head] = e;
    }
}

// ---------------------------------------------------------------------------
// Kernel B: per (b,i): stream dis (depth-2 prefetch), logits, softmax,
// out = attn @ g.  4 blocks/SM.
// ---------------------------------------------------------------------------
__global__ void __launch_bounds__(256, 4) attn_kernel(const float* __restrict__ dis,
                                                      const int*   __restrict__ adj,
                                                      float*       __restrict__ out)
{
    __shared__ float esh2[Nn * Hh];      // [j][h] logits -> probs
    __shared__ float sjsh[Nn * Hh];      // [j][h]
    __shared__ float si_sh[Hh];
    __shared__ float inv_sh[Hh];
    __shared__ float part[Hh][Dd];       // stage-3 partials [warp][d]
    __shared__ int   adjsh[Nn];

    int tid  = threadIdx.x;
    int lane = tid & 31;
    int warp = tid >> 5;                 // 0..7
    int row  = blockIdx.x;               // b*200 + i
    int b    = row / Nn;
    size_t rb = (size_t)row * Nn;

    for (int idx = tid; idx < Nn * Hh; idx += 256)
        sjsh[idx] = sj_buf[(size_t)b * Nn * Hh + idx];
    for (int idx = tid; idx < Nn; idx += 256)
        adjsh[idx] = adj[rb + idx];
    if (tid < Hh) si_sh[tid] = si_buf[row * Hh + tid];

    // Per-lane slice of c3: lane covers d = lane*4..+3, all 8 heads.
    float c3r[32];
    {
        const float4* cv = (const float4*)c3g;
        #pragma unroll
        for (int t2 = 0; t2 < 8; t2++)
            ((float4*)c3r)[t2] = cv[lane * 8 + t2];
    }
    __syncthreads();

    float4 si0 = *(const float4*)&si_sh[0];
    float4 si1 = *(const float4*)&si_sh[4];

    // ---- Stage 1: warp w handles j = w + 8t, t = 0..24. Depth-2 prefetch.
    const float4* disv = (const float4*)dis;
    #pragma unroll 1
    for (int c = 0; c < 12; c++) {
        float4 dv[2];
        dv[0] = disv[(rb + warp + 8 * (2 * c))     * 32 + lane];
        dv[1] = disv[(rb + warp + 8 * (2 * c + 1)) * 32 + lane];
        process_j(dv[0], warp + 8 * (2 * c),     lane, c3r, si0, si1, sjsh, adjsh, esh2);
        process_j(dv[1], warp + 8 * (2 * c + 1), lane, c3r, si0, si1, sjsh, adjsh, esh2);
    }
    {   // tail t = 24
        int jj = warp + 192;
        float4 dv = disv[(rb + jj) * 32 + lane];
        process_j(dv, jj, lane, c3r, si0, si1, sjsh, adjsh, esh2);
    }
    __syncthreads();

    // ---- Stage 2: softmax over j, one warp per head.
    {
        int hh = warp;
        float m = -INFINITY;
        for (int j = lane; j < Nn; j += 32)
            m = fmaxf(m, esh2[j * Hh + hh]);
        #pragma unroll
        for (int o = 16; o > 0; o >>= 1)
            m = fmaxf(m, __shfl_xor_sync(0xffffffffu, m, o));
        float s = 0.f;
        for (int j = lane; j < Nn; j += 32) {
            float p = __expf(esh2[j * Hh + hh] - m);
            esh2[j * Hh + hh] = p;
            s += p;
        }
        #pragma unroll
        for (int o = 16; o > 0; o >>= 1)
            s += __shfl_xor_sync(0xffffffffu, s, o);
        if (lane == 0) inv_sh[hh] = 1.f / s;
    }
    __syncthreads();

    // ---- Stage 3: out[d] = (1/s) * sum_j p[j][h(d)] * g[b,j,d].
    {
        const float4* gvec = (const float4*)g_buf;
        size_t gb = (size_t)b * Nn;
        int myh = lane >> 2;
        float ax = 0.f, ay = 0.f, az = 0.f, aw = 0.f;
        #pragma unroll 1
        for (int c = 0; c < 12; c++) {
            float4 gv[2]; float p[2];
            #pragma unroll
            for (int u = 0; u < 2; u++) {
                int jj = warp + 8 * (2 * c + u);
                gv[u] = gvec[(gb + jj) * 32 + lane];
                p[u]  = esh2[jj * Hh + myh];
            }
            #pragma unroll
            for (int u = 0; u < 2; u++) {
                ax += p[u] * gv[u].x;  ay += p[u] * gv[u].y;
                az += p[u] * gv[u].z;  aw += p[u] * gv[u].w;
            }
        }
        {
            int jj = warp + 192;
            float4 gv = gvec[(gb + jj) * 32 + lane];
            float  p  = esh2[jj * Hh + myh];
            ax += p * gv.x;  ay += p * gv.y;  az += p * gv.z;  aw += p * gv.w;
        }
        *(float4*)&part[warp][lane * 4] = make_float4(ax, ay, az, aw);
        __syncthreads();
        if (tid < Dd) {
            int d = tid;
            float s = 0.f;
            #pragma unroll
            for (int w = 0; w < Hh; w++) s += part[w][d];
            out[(size_t)row * Dd + d] = s * inv_sh[d >> 4];
        }
    }
}

// ---------------------------------------------------------------------------
extern "C" void kernel_launch(void* const* d_in, const int* in_sizes, int n_in,
                              void* d_out, int out_size)
{
    const float* h   = (const float*)d_in[0];
    const int*   adj = (const int*)  d_in[1];
    const float* dis = (const float*)d_in[2];
    const float* W   = (const float*)d_in[3];
    const float* We  = (const float*)d_in[4];
    const float* a   = (const float*)d_in[5];
    float* out = (float*)d_out;

    gemm_fused<<<208, 256>>>(h, W, We, a);
    attn_kernel<<<ROWS, 256>>>(dis, adj, out);
}

// round 8
// speedup vs baseline: 1.2772x; 1.2772x over previous
#include <cuda_runtime.h>
#include <math.h>
#include <stdint.h>

#define Bb 16
#define Nn 200
#define Dd 128
#define Hh 8
#define ROWS (Bb*Nn)          // 3200
#define NEG_SLOPE 0.2f
#define RPB 16                // rows per gemm block
#define HS 20                 // hT row stride (floats)
#define RING 8                // cp.async ring slots per warp

// Scratch (static device globals — no allocation)
__device__ float g_buf[ROWS * Dd];      // g = h @ W           (1.6 MB)
__device__ float si_buf[ROWS * Hh];     // s_i
__device__ float sj_buf[ROWS * Hh];     // s_j
__device__ float c3g[Dd * Hh];          // W_e folded with a3

__device__ __forceinline__ void cp_async16(uint32_t smem_addr, const void* gptr) {
    asm volatile("cp.async.cg.shared.global [%0], [%1], 16;\n"
                 :: "r"(smem_addr), "l"(gptr));
}
#define CP_COMMIT()  asm volatile("cp.async.commit_group;\n" ::: "memory")
#define CP_WAIT(N)   asm volatile("cp.async.wait_group %0;\n" :: "n"(N) : "memory")

// ---------------------------------------------------------------------------
// Kernel A: blocks 0..199: g = h @ W (W via L1, hT in 10KB smem),
//           s_i/s_j fused from live accumulators.
//           blocks 200..207: c3[d][h] = sum_q W_e[d,h*16+q]*a3[q].
// ---------------------------------------------------------------------------
__global__ void __launch_bounds__(256) gemm_fused(const float* __restrict__ h,
                                                  const float* __restrict__ W,
                                                  const float* __restrict__ We,
                                                  const float* __restrict__ a)
{
    __shared__ float hT[Dd * HS];
    __shared__ float ash[48];

    int t = threadIdx.x;

    if (blockIdx.x >= 200) {             // ---- c3 path (one head per block)
        int hd = blockIdx.x - 200;
        __shared__ float a3sh[16];
        if (t < 16) a3sh[t] = a[32 + t];
        __syncthreads();
        if (t < Dd) {
            const float4* row = (const float4*)(We + (size_t)t * Dd + hd * 16);
            float s = 0.f;
            #pragma unroll
            for (int qv = 0; qv < 4; qv++) {
                float4 w4 = row[qv];
                s += w4.x * a3sh[qv * 4 + 0] + w4.y * a3sh[qv * 4 + 1]
                   + w4.z * a3sh[qv * 4 + 2] + w4.w * a3sh[qv * 4 + 3];
            }
            c3g[t * Hh + hd] = s;
        }
        return;
    }

    int row0 = blockIdx.x * RPB;
    if (t < 32) ash[t] = a[t];

    #pragma unroll 2
    for (int idx = t; idx < RPB * Dd; idx += 256) {
        int r = idx >> 7, k = idx & 127;
        hT[k * HS + r] = h[(size_t)(row0 + r) * Dd + k];
    }
    __syncthreads();

    int cvec = t & 31;
    int c0   = cvec * 4;
    int r0   = (t >> 5) * 2;
    float acc0[4] = {0.f, 0.f, 0.f, 0.f};
    float acc1[4] = {0.f, 0.f, 0.f, 0.f};

    const float4* Wv = (const float4*)W;
    #pragma unroll 8
    for (int k = 0; k < Dd; k++) {
        float4 w4 = Wv[k * 32 + cvec];
        float2 h2 = *(const float2*)&hT[k * HS + r0];
        acc0[0] += h2.x * w4.x;  acc0[1] += h2.x * w4.y;
        acc0[2] += h2.x * w4.z;  acc0[3] += h2.x * w4.w;
        acc1[0] += h2.y * w4.x;  acc1[1] += h2.y * w4.y;
        acc1[2] += h2.y * w4.z;  acc1[3] += h2.y * w4.w;
    }
    *(float4*)&g_buf[(size_t)(row0 + r0)     * Dd + c0] =
        make_float4(acc0[0], acc0[1], acc0[2], acc0[3]);
    *(float4*)&g_buf[(size_t)(row0 + r0 + 1) * Dd + c0] =
        make_float4(acc1[0], acc1[1], acc1[2], acc1[3]);

    {   // fused s_i / s_j
        int head = c0 >> 4;
        int qb   = c0 & 15;
        const float* a1 = ash;
        const float* a2 = ash + 16;
        float pi0 = acc0[0]*a1[qb] + acc0[1]*a1[qb+1] + acc0[2]*a1[qb+2] + acc0[3]*a1[qb+3];
        float pj0 = acc0[0]*a2[qb] + acc0[1]*a2[qb+1] + acc0[2]*a2[qb+2] + acc0[3]*a2[qb+3];
        float pi1 = acc1[0]*a1[qb] + acc1[1]*a1[qb+1] + acc1[2]*a1[qb+2] + acc1[3]*a1[qb+3];
        float pj1 = acc1[0]*a2[qb] + acc1[1]*a2[qb+1] + acc1[2]*a2[qb+2] + acc1[3]*a2[qb+3];
        pi0 += __shfl_xor_sync(0xffffffffu, pi0, 1);
        pi0 += __shfl_xor_sync(0xffffffffu, pi0, 2);
        pj0 += __shfl_xor_sync(0xffffffffu, pj0, 1);
        pj0 += __shfl_xor_sync(0xffffffffu, pj0, 2);
        pi1 += __shfl_xor_sync(0xffffffffu, pi1, 1);
        pi1 += __shfl_xor_sync(0xffffffffu, pi1, 2);
        pj1 += __shfl_xor_sync(0xffffffffu, pj1, 1);
        pj1 += __shfl_xor_sync(0xffffffffu, pj1, 2);
        if ((t & 3) == 0) {
            si_buf[(row0 + r0)     * Hh + head] = pi0;
            sj_buf[(row0 + r0)     * Hh + head] = pj0;
            si_buf[(row0 + r0 + 1) * Hh + head] = pi1;
            sj_buf[(row0 + r0 + 1) * Hh + head] = pj1;
        }
    }
}

// ---------------------------------------------------------------------------
// Kernel B: per (b,i). Stage 1 streams dis through per-warp cp.async rings
// (8 slots x 512B, barrier-free); butterfly reduce -> logits. Softmax.
// Stage 3 streams g rows through the same rings.
// ---------------------------------------------------------------------------
__global__ void __launch_bounds__(256, 4) attn_kernel(const float* __restrict__ dis,
                                                      const int*   __restrict__ adj,
                                                      float*       __restrict__ out)
{
    __shared__ __align__(16) float ring[Hh * RING * Dd];   // 32 KB
    __shared__ __align__(16) float esh2[Nn * Hh];          // 6.4 KB [j][h]
    __shared__ __align__(16) float sjsh[Nn * Hh];          // 6.4 KB; aliased as part[] in stage 3
    __shared__ int   adjsh[Nn];
    __shared__ float si_sh[Hh];
    __shared__ float inv_sh[Hh];

    int tid  = threadIdx.x;
    int lane = tid & 31;
    int warp = tid >> 5;                 // 0..7
    int row  = blockIdx.x;               // b*200 + i
    int b    = row / Nn;
    size_t rb = (size_t)row * Nn;

    // Preloads (overlap with stage-1 prologue issuance below is fine).
    for (int idx = tid; idx < Nn * Hh; idx += 256)
        sjsh[idx] = sj_buf[(size_t)b * Nn * Hh + idx];
    for (int idx = tid; idx < Nn; idx += 256)
        adjsh[idx] = adj[rb + idx];
    if (tid < Hh) si_sh[tid] = si_buf[row * Hh + tid];

    // Per-lane slice of c3: lane covers d = lane*4..+3, all 8 heads.
    float c3r[32];
    {
        const float4* cv = (const float4*)c3g;
        #pragma unroll
        for (int t2 = 0; t2 < 8; t2++)
            ((float4*)c3r)[t2] = cv[lane * 8 + t2];
    }
    __syncthreads();

    // Per-warp ring base; lane L owns bytes [L*16, L*16+16) of each slot.
    float* ringw = ring + warp * RING * Dd;
    uint32_t ring_sa = (uint32_t)__cvta_generic_to_shared(ringw) + lane * 16;

    // ---- Stage 1: warp w handles j = w + 8t, t = 0..24.
    {
        const float* disw = dis + (rb + warp) * (size_t)Dd + lane * 4;
        #pragma unroll
        for (int s = 0; s < RING; s++) {
            cp_async16(ring_sa + s * 512, disw + (size_t)(8 * s) * Dd);
            CP_COMMIT();
        }
        for (int t = 0; t < 25; t++) {
            CP_WAIT(7);
            int slot = t & 7;
            float4 dv = *(const float4*)(ringw + slot * Dd + lane * 4);

            float v[8];
            #pragma unroll
            for (int h = 0; h < 8; h++)
                v[h] = dv.x * c3r[h]      + dv.y * c3r[8 + h]
                     + dv.z * c3r[16 + h] + dv.w * c3r[24 + h];

            // Head-folding butterfly (9 shfl): lane h*4 ends with head h total.
            float w4[4];
            {
                bool hi = (lane & 16) != 0;
                #pragma unroll
                for (int k = 0; k < 4; k++) {
                    float send = hi ? v[k] : v[k + 4];
                    float recv = __shfl_xor_sync(0xffffffffu, send, 16);
                    w4[k] = (hi ? v[k + 4] : v[k]) + recv;
                }
            }
            float w2[2];
            {
                bool hi = (lane & 8) != 0;
                #pragma unroll
                for (int k = 0; k < 2; k++) {
                    float send = hi ? w4[k] : w4[k + 2];
                    float recv = __shfl_xor_sync(0xffffffffu, send, 8);
                    w2[k] = (hi ? w4[k + 2] : w4[k]) + recv;
                }
            }
            float y;
            {
                bool hi = (lane & 4) != 0;
                float send = hi ? w2[0] : w2[1];
                float recv = __shfl_xor_sync(0xffffffffu, send, 4);
                y = (hi ? w2[1] : w2[0]) + recv;
            }
            y += __shfl_xor_sync(0xffffffffu, y, 1);
            y += __shfl_xor_sync(0xffffffffu, y, 2);

            int jj = warp + 8 * t;
            if ((lane & 3) == 0) {
                int head = lane >> 2;
                float e = si_sh[head] + sjsh[jj * Hh + head] + y;
                e = (e > 0.f) ? e : NEG_SLOPE * e;
                if (adjsh[jj] == 0) e = -INFINITY;
                esh2[jj * Hh + head] = e;
            }

            int tn = t + RING;
            if (tn < 25)
                cp_async16(ring_sa + (tn & 7) * 512, disw + (size_t)(8 * tn) * Dd);
            CP_COMMIT();
        }
    }
    __syncthreads();

    // ---- Stage 2: softmax over j, one warp per head.
    {
        int hh = warp;
        float m = -INFINITY;
        for (int j = lane; j < Nn; j += 32)
            m = fmaxf(m, esh2[j * Hh + hh]);
        #pragma unroll
        for (int o = 16; o > 0; o >>= 1)
            m = fmaxf(m, __shfl_xor_sync(0xffffffffu, m, o));
        float s = 0.f;
        for (int j = lane; j < Nn; j += 32) {
            float p = __expf(esh2[j * Hh + hh] - m);
            esh2[j * Hh + hh] = p;
            s += p;
        }
        #pragma unroll
        for (int o = 16; o > 0; o >>= 1)
            s += __shfl_xor_sync(0xffffffffu, s, o);
        if (lane == 0) inv_sh[hh] = 1.f / s;
    }
    __syncthreads();

    // ---- Stage 3: out[d] = (1/s) * sum_j p[j][h(d)] * g[b,j,d]  via rings.
    {
        CP_WAIT(0);   // drain stage-1 groups before reusing slots
        const float* gw = g_buf + ((size_t)b * Nn + warp) * Dd + lane * 4;
        int myh = lane >> 2;
        float ax = 0.f, ay = 0.f, az = 0.f, aw = 0.f;

        #pragma unroll
        for (int s = 0; s < RING; s++) {
            cp_async16(ring_sa + s * 512, gw + (size_t)(8 * s) * Dd);
            CP_COMMIT();
        }
        for (int t = 0; t < 25; t++) {
            CP_WAIT(7);
            int slot = t & 7;
            float4 gv = *(const float4*)(ringw + slot * Dd + lane * 4);
            int jj = warp + 8 * t;
            float p = esh2[jj * Hh + myh];
            ax += p * gv.x;  ay += p * gv.y;  az += p * gv.z;  aw += p * gv.w;

            int tn = t + RING;
            if (tn < 25)
                cp_async16(ring_sa + (tn & 7) * 512, gw + (size_t)(8 * tn) * Dd);
            CP_COMMIT();
        }

        float* part = sjsh;                     // alias (sjsh dead now)
        *(float4*)&part[warp * Dd + lane * 4] = make_float4(ax, ay, az, aw);
        __syncthreads();
        if (tid < Dd) {
            int d = tid;
            float s = 0.f;
            #pragma unroll
            for (int w = 0; w < Hh; w++) s += part[w * Dd + d];
            out[(size_t)row * Dd + d] = s * inv_sh[d >> 4];
        }
    }
}

// ---------------------------------------------------------------------------
extern "C" void kernel_launch(void* const* d_in, const int* in_sizes, int n_in,
                              void* d_out, int out_size)
{
    const float* h   = (const float*)d_in[0];
    const int*   adj = (const int*)  d_in[1];
    const float* dis = (const float*)d_in[2];
    const float* W   = (const float*)d_in[3];
    const float* We  = (const float*)d_in[4];
    const float* a   = (const float*)d_in[5];
    float* out = (float*)d_out;

    gemm_fused<<<208, 256>>>(h, W, We, a);
    attn_kernel<<<ROWS, 256>>>(dis, adj, out);
}

// round 9
// speedup vs baseline: 1.6548x; 1.2956x over previous
#include <cuda_runtime.h>
#include <math.h>
#include <stdint.h>

#define Bb 16
#define Nn 200
#define Dd 128
#define Hh 8
#define ROWS (Bb*Nn)          // 3200
#define NEG_SLOPE 0.2f
#define RPB 16                // rows per gemm block
#define HS 20                 // hT row stride (floats)
#define ES9 9                 // esh2 row stride (conflict-free softmax)

// Scratch (static device globals — no allocation)
__device__ float g_buf[ROWS * Dd];      // g = h @ W           (1.6 MB)
__device__ float si_buf[ROWS * Hh];     // s_i
__device__ float sj_buf[ROWS * Hh];     // s_j
__device__ float c3g[Dd * Hh];          // W_e folded with a3   [d][h]

__device__ __forceinline__ void cp_async16(uint32_t smem_addr, const void* gptr) {
    asm volatile("cp.async.cg.shared.global [%0], [%1], 16;\n"
                 :: "r"(smem_addr), "l"(gptr));
}
#define CP_COMMIT()  asm volatile("cp.async.commit_group;\n" ::: "memory")
#define CP_WAIT0()   asm volatile("cp.async.wait_group 0;\n" ::: "memory")

__device__ __forceinline__ uint32_t f2tf32(float x) {
    uint32_t r; asm("cvt.rna.tf32.f32 %0, %1;" : "=r"(r) : "f"(x)); return r;
}
__device__ __forceinline__ void ldm4(uint32_t& r0, uint32_t& r1, uint32_t& r2,
                                     uint32_t& r3, uint32_t addr) {
    asm volatile("ldmatrix.sync.aligned.m8n8.x4.shared.b16 {%0,%1,%2,%3}, [%4];"
                 : "=r"(r0), "=r"(r1), "=r"(r2), "=r"(r3) : "r"(addr));
}
__device__ __forceinline__ void mma_tf32(float& d0, float& d1, float& d2, float& d3,
                                         uint32_t a0, uint32_t a1, uint32_t a2,
                                         uint32_t a3, uint32_t b0, uint32_t b1) {
    asm volatile("mma.sync.aligned.m16n8k8.row.col.f32.tf32.tf32.f32 "
                 "{%0,%1,%2,%3}, {%4,%5,%6,%7}, {%8,%9}, {%0,%1,%2,%3};"
                 : "+f"(d0), "+f"(d1), "+f"(d2), "+f"(d3)
                 : "r"(a0), "r"(a1), "r"(a2), "r"(a3), "r"(b0), "r"(b1));
}

// ---------------------------------------------------------------------------
// Kernel A: blocks 0..199: g = h @ W (W via L1, hT in 10KB smem),
//           s_i/s_j fused from live accumulators.
//           blocks 200..207: c3[d][h] = sum_q W_e[d,h*16+q]*a3[q].
// ---------------------------------------------------------------------------
__global__ void __launch_bounds__(256) gemm_fused(const float* __restrict__ h,
                                                  const float* __restrict__ W,
                                                  const float* __restrict__ We,
                                                  const float* __restrict__ a)
{
    __shared__ float hT[Dd * HS];
    __shared__ float ash[48];

    int t = threadIdx.x;

    if (blockIdx.x >= 200) {             // ---- c3 path (one head per block)
        int hd = blockIdx.x - 200;
        __shared__ float a3sh[16];
        if (t < 16) a3sh[t] = a[32 + t];
        __syncthreads();
        if (t < Dd) {
            const float4* row = (const float4*)(We + (size_t)t * Dd + hd * 16);
            float s = 0.f;
            #pragma unroll
            for (int qv = 0; qv < 4; qv++) {
                float4 w4 = row[qv];
                s += w4.x * a3sh[qv * 4 + 0] + w4.y * a3sh[qv * 4 + 1]
                   + w4.z * a3sh[qv * 4 + 2] + w4.w * a3sh[qv * 4 + 3];
            }
            c3g[t * Hh + hd] = s;
        }
        return;
    }

    int row0 = blockIdx.x * RPB;
    if (t < 32) ash[t] = a[t];

    #pragma unroll 2
    for (int idx = t; idx < RPB * Dd; idx += 256) {
        int r = idx >> 7, k = idx & 127;
        hT[k * HS + r] = h[(size_t)(row0 + r) * Dd + k];
    }
    __syncthreads();

    int cvec = t & 31;
    int c0   = cvec * 4;
    int r0   = (t >> 5) * 2;
    float acc0[4] = {0.f, 0.f, 0.f, 0.f};
    float acc1[4] = {0.f, 0.f, 0.f, 0.f};

    const float4* Wv = (const float4*)W;
    #pragma unroll 8
    for (int k = 0; k < Dd; k++) {
        float4 w4 = Wv[k * 32 + cvec];
        float2 h2 = *(const float2*)&hT[k * HS + r0];
        acc0[0] += h2.x * w4.x;  acc0[1] += h2.x * w4.y;
        acc0[2] += h2.x * w4.z;  acc0[3] += h2.x * w4.w;
        acc1[0] += h2.y * w4.x;  acc1[1] += h2.y * w4.y;
        acc1[2] += h2.y * w4.z;  acc1[3] += h2.y * w4.w;
    }
    *(float4*)&g_buf[(size_t)(row0 + r0)     * Dd + c0] =
        make_float4(acc0[0], acc0[1], acc0[2], acc0[3]);
    *(float4*)&g_buf[(size_t)(row0 + r0 + 1) * Dd + c0] =
        make_float4(acc1[0], acc1[1], acc1[2], acc1[3]);

    {   // fused s_i / s_j
        int head = c0 >> 4;
        int qb   = c0 & 15;
        const float* a1 = ash;
        const float* a2 = ash + 16;
        float pi0 = acc0[0]*a1[qb] + acc0[1]*a1[qb+1] + acc0[2]*a1[qb+2] + acc0[3]*a1[qb+3];
        float pj0 = acc0[0]*a2[qb] + acc0[1]*a2[qb+1] + acc0[2]*a2[qb+2] + acc0[3]*a2[qb+3];
        float pi1 = acc1[0]*a1[qb] + acc1[1]*a1[qb+1] + acc1[2]*a1[qb+2] + acc1[3]*a1[qb+3];
        float pj1 = acc1[0]*a2[qb] + acc1[1]*a2[qb+1] + acc1[2]*a2[qb+2] + acc1[3]*a2[qb+3];
        pi0 += __shfl_xor_sync(0xffffffffu, pi0, 1);
        pi0 += __shfl_xor_sync(0xffffffffu, pi0, 2);
        pj0 += __shfl_xor_sync(0xffffffffu, pj0, 1);
        pj0 += __shfl_xor_sync(0xffffffffu, pj0, 2);
        pi1 += __shfl_xor_sync(0xffffffffu, pi1, 1);
        pi1 += __shfl_xor_sync(0xffffffffu, pi1, 2);
        pj1 += __shfl_xor_sync(0xffffffffu, pj1, 1);
        pj1 += __shfl_xor_sync(0xffffffffu, pj1, 2);
        if ((t & 3) == 0) {
            si_buf[(row0 + r0)     * Hh + head] = pi0;
            sj_buf[(row0 + r0)     * Hh + head] = pj0;
            si_buf[(row0 + r0 + 1) * Hh + head] = pi1;
            sj_buf[(row0 + r0 + 1) * Hh + head] = pj1;
        }
    }
}

// ---------------------------------------------------------------------------
// Kernel B: per (b,i). Stage 1: s_e = dis_tile @ c3 on TENSOR CORES (3xTF32),
// warp-private swizzled cp.async tiles + ldmatrix. Stage 2 softmax.
// Stage 3 direct-LDG attn @ g.
// ---------------------------------------------------------------------------
__global__ void __launch_bounds__(256, 4) attn_kernel(const float* __restrict__ dis,
                                                      const int*   __restrict__ adj,
                                                      float*       __restrict__ out)
{
    __shared__ __align__(16) float    bufs[8 * 512];      // 8 warps x 2KB tiles
    __shared__ __align__(16) float    esh2[208 * ES9];    // [j][h] stride 9
    __shared__ __align__(16) float    sjsh[Nn * Hh];      // [j][h]; part[] alias later
    __shared__ uint32_t c3hi_s[Dd * Hh];                  // tf32 hi of c3 [d][h]
    __shared__ uint32_t c3lo_s[Dd * Hh];                  // tf32 lo of c3
    __shared__ int   adjsh[Nn];
    __shared__ float si_sh[Hh];
    __shared__ float inv_sh[Hh];

    int tid  = threadIdx.x;
    int lane = tid & 31;
    int warp = tid >> 5;                 // 0..7
    int row  = blockIdx.x;               // b*200 + i
    int b    = row / Nn;
    size_t rb = (size_t)row * Nn;

    // Prologue loads
    for (int idx = tid; idx < Nn * Hh; idx += 256)
        sjsh[idx] = sj_buf[(size_t)b * Nn * Hh + idx];
    for (int idx = tid; idx < Nn; idx += 256)
        adjsh[idx] = adj[rb + idx];
    if (tid < Hh) si_sh[tid] = si_buf[row * Hh + tid];
    for (int idx = tid; idx < Dd * Hh; idx += 256) {
        float v = c3g[idx];
        uint32_t hi = f2tf32(v);
        c3hi_s[idx] = hi;
        c3lo_s[idx] = f2tf32(v - __uint_as_float(hi));
    }
    __syncthreads();

    uint32_t buf_sa = (uint32_t)__cvta_generic_to_shared(bufs) + warp * 2048;
    int g4 = lane >> 2;                  // groupID
    int t4 = lane & 3;                   // threadID-in-group

    // ---- Stage 1: chunks of 16 j-rows; warp w owns chunks {w, w+8} (<13).
    #pragma unroll 1
    for (int ci = 0; ci < 2; ci++) {
        int chunk = warp + ci * 8;
        if (chunk >= 13) break;
        int j0 = chunk * 16;

        float d0 = 0.f, d1 = 0.f, d2 = 0.f, d3 = 0.f;

        #pragma unroll 1
        for (int kb = 0; kb < 4; kb++) {
            // Fill 16 rows x 32 cols (swizzled 16B units) via cp.async.
            #pragma unroll
            for (int it = 0; it < 4; it++) {
                int idx = it * 32 + lane;
                int r = idx >> 3, u = idx & 7;
                int j = j0 + r;  if (j > 199) j = 199;
                const float* src = dis + (rb + j) * (size_t)Dd + kb * 32 + u * 4;
                cp_async16(buf_sa + (uint32_t)((r * 8 + (u ^ (r & 7))) * 16), src);
            }
            CP_COMMIT();
            CP_WAIT0();
            __syncwarp();

            // 4 k-steps of 8 within this 32-col block.
            #pragma unroll
            for (int s = 0; s < 4; s++) {
                int mi = lane >> 3, ri = lane & 7;
                int rr = ri + 8 * (mi & 1);
                int uu = 2 * s + (mi >> 1);
                uint32_t a0, a1, a2, a3;
                ldm4(a0, a1, a2, a3,
                     buf_sa + (uint32_t)((rr * 8 + (uu ^ (rr & 7))) * 16));

                // 3xTF32 split
                uint32_t ah0 = f2tf32(__uint_as_float(a0));
                uint32_t ah1 = f2tf32(__uint_as_float(a1));
                uint32_t ah2 = f2tf32(__uint_as_float(a2));
                uint32_t ah3 = f2tf32(__uint_as_float(a3));
                uint32_t al0 = f2tf32(__uint_as_float(a0) - __uint_as_float(ah0));
                uint32_t al1 = f2tf32(__uint_as_float(a1) - __uint_as_float(ah1));
                uint32_t al2 = f2tf32(__uint_as_float(a2) - __uint_as_float(ah2));
                uint32_t al3 = f2tf32(__uint_as_float(a3) - __uint_as_float(ah3));

                int kB = kb * 32 + s * 8 + t4;       // B row (k), col = head g4
                uint32_t bh0 = c3hi_s[kB * Hh + g4];
                uint32_t bh1 = c3hi_s[(kB + 4) * Hh + g4];
                uint32_t bl0 = c3lo_s[kB * Hh + g4];
                uint32_t bl1 = c3lo_s[(kB + 4) * Hh + g4];

                mma_tf32(d0, d1, d2, d3, ah0, ah1, ah2, ah3, bh0, bh1);
                mma_tf32(d0, d1, d2, d3, al0, al1, al2, al3, bh0, bh1);
                mma_tf32(d0, d1, d2, d3, ah0, ah1, ah2, ah3, bl0, bl1);
            }
        }

        // Epilogue: D frag -> masked leaky-relu logits in esh2[j][h].
        {
            int h0 = 2 * t4, h1 = h0 + 1;
            int jA = j0 + g4;
            if (jA < 200) {
                float e0 = d0 + si_sh[h0] + sjsh[jA * Hh + h0];
                float e1 = d1 + si_sh[h1] + sjsh[jA * Hh + h1];
                e0 = (e0 > 0.f) ? e0 : NEG_SLOPE * e0;
                e1 = (e1 > 0.f) ? e1 : NEG_SLOPE * e1;
                if (adjsh[jA] == 0) { e0 = -INFINITY; e1 = -INFINITY; }
                esh2[jA * ES9 + h0] = e0;
                esh2[jA * ES9 + h1] = e1;
            }
            int jB = j0 + 8 + g4;
            if (jB < 200) {
                float e2 = d2 + si_sh[h0] + sjsh[jB * Hh + h0];
                float e3 = d3 + si_sh[h1] + sjsh[jB * Hh + h1];
                e2 = (e2 > 0.f) ? e2 : NEG_SLOPE * e2;
                e3 = (e3 > 0.f) ? e3 : NEG_SLOPE * e3;
                if (adjsh[jB] == 0) { e2 = -INFINITY; e3 = -INFINITY; }
                esh2[jB * ES9 + h0] = e2;
                esh2[jB * ES9 + h1] = e3;
            }
        }
    }
    __syncthreads();

    // ---- Stage 2: softmax over j, one warp per head (stride-9: no conflicts).
    {
        int hh = warp;
        float m = -INFINITY;
        for (int j = lane; j < Nn; j += 32)
            m = fmaxf(m, esh2[j * ES9 + hh]);
        #pragma unroll
        for (int o = 16; o > 0; o >>= 1)
            m = fmaxf(m, __shfl_xor_sync(0xffffffffu, m, o));
        float s = 0.f;
        for (int j = lane; j < Nn; j += 32) {
            float p = __expf(esh2[j * ES9 + hh] - m);
            esh2[j * ES9 + hh] = p;
            s += p;
        }
        #pragma unroll
        for (int o = 16; o > 0; o >>= 1)
            s += __shfl_xor_sync(0xffffffffu, s, o);
        if (lane == 0) inv_sh[hh] = 1.f / s;
    }
    __syncthreads();

    // ---- Stage 3: out[d] = (1/s) * sum_j p[j][h(d)] * g[b,j,d]. Direct LDG.
    {
        const float4* gvec = (const float4*)g_buf;
        size_t gb = (size_t)b * Nn;
        int myh = lane >> 2;
        float ax = 0.f, ay = 0.f, az = 0.f, aw = 0.f;
        #pragma unroll 1
        for (int c = 0; c < 4; c++) {
            float4 gv[6]; float p[6];
            #pragma unroll
            for (int u = 0; u < 6; u++) {
                int jj = warp + 8 * (c * 6 + u);
                gv[u] = gvec[(gb + jj) * 32 + lane];
                p[u]  = esh2[jj * ES9 + myh];
            }
            #pragma unroll
            for (int u = 0; u < 6; u++) {
                ax += p[u] * gv[u].x;  ay += p[u] * gv[u].y;
                az += p[u] * gv[u].z;  aw += p[u] * gv[u].w;
            }
        }
        {
            int jj = warp + 192;
            float4 gv = gvec[(gb + jj) * 32 + lane];
            float  p  = esh2[jj * ES9 + myh];
            ax += p * gv.x;  ay += p * gv.y;  az += p * gv.z;  aw += p * gv.w;
        }
        float* part = sjsh;                     // alias (sjsh dead now)
        *(float4*)&part[warp * Dd + lane * 4] = make_float4(ax, ay, az, aw);
        __syncthreads();
        if (tid < Dd) {
            int d = tid;
            float s = 0.f;
            #pragma unroll
            for (int w = 0; w < Hh; w++) s += part[w * Dd + d];
            out[(size_t)row * Dd + d] = s * inv_sh[d >> 4];
        }
    }
}

// ---------------------------------------------------------------------------
extern "C" void kernel_launch(void* const* d_in, const int* in_sizes, int n_in,
                              void* d_out, int out_size)
{
    const float* h   = (const float*)d_in[0];
    const int*   adj = (const int*)  d_in[1];
    const float* dis = (const float*)d_in[2];
    const float* W   = (const float*)d_in[3];
    const float* We  = (const float*)d_in[4];
    const float* a   = (const float*)d_in[5];
    float* out = (float*)d_out;

    gemm_fused<<<208, 256>>>(h, W, We, a);
    attn_kernel<<<ROWS, 256>>>(dis, adj, out);
}

// round 10
// speedup vs baseline: 1.8385x; 1.1110x over previous
#include <cuda_runtime.h>
#include <math.h>
#include <stdint.h>

#define Bb 16
#define Nn 200
#define Dd 128
#define Hh 8
#define ROWS (Bb*Nn)          // 3200
#define NEG_SLOPE 0.2f
#define RPB 16                // rows per gemm block
#define HS 20                 // hT row stride (floats)
#define ES9 9                 // esh2 row stride (conflict-free softmax)

// attn dynamic smem layout (floats)
#define SM_BUFS   0                       // 8 warps x 2 slots x 512 = 8192
#define SM_ESH    8192                    // 208*9 = 1872
#define SM_SJ     (SM_ESH + 1872)         // 1600
#define SM_C3HI   (SM_SJ + 1600)          // 1024
#define SM_C3LO   (SM_C3HI + 1024)        // 1024
#define SM_ADJ    (SM_C3LO + 1024)        // 200
#define SM_SI     (SM_ADJ + 200)          // 8
#define SM_INV    (SM_SI + 8)             // 8
#define SM_TOTALF (SM_INV + 8)            // 13928 floats = 55712 B

// Scratch (static device globals — no allocation)
__device__ float g_buf[ROWS * Dd];      // g = h @ W           (1.6 MB)
__device__ float si_buf[ROWS * Hh];     // s_i
__device__ float sj_buf[ROWS * Hh];     // s_j
__device__ float c3g[Dd * Hh];          // W_e folded with a3   [d][h]

__device__ __forceinline__ void cp_async16(uint32_t smem_addr, const void* gptr) {
    asm volatile("cp.async.cg.shared.global [%0], [%1], 16;\n"
                 :: "r"(smem_addr), "l"(gptr));
}
#define CP_COMMIT()  asm volatile("cp.async.commit_group;\n" ::: "memory")
#define CP_WAIT1()   asm volatile("cp.async.wait_group 1;\n" ::: "memory")

__device__ __forceinline__ uint32_t f2tf32(float x) {
    uint32_t r; asm("cvt.rna.tf32.f32 %0, %1;" : "=r"(r) : "f"(x)); return r;
}
__device__ __forceinline__ void ldm4(uint32_t& r0, uint32_t& r1, uint32_t& r2,
                                     uint32_t& r3, uint32_t addr) {
    asm volatile("ldmatrix.sync.aligned.m8n8.x4.shared.b16 {%0,%1,%2,%3}, [%4];"
                 : "=r"(r0), "=r"(r1), "=r"(r2), "=r"(r3) : "r"(addr));
}
__device__ __forceinline__ void mma_tf32(float& d0, float& d1, float& d2, float& d3,
                                         uint32_t a0, uint32_t a1, uint32_t a2,
                                         uint32_t a3, uint32_t b0, uint32_t b1) {
    asm volatile("mma.sync.aligned.m16n8k8.row.col.f32.tf32.tf32.f32 "
                 "{%0,%1,%2,%3}, {%4,%5,%6,%7}, {%8,%9}, {%0,%1,%2,%3};"
                 : "+f"(d0), "+f"(d1), "+f"(d2), "+f"(d3)
                 : "r"(a0), "r"(a1), "r"(a2), "r"(a3), "r"(b0), "r"(b1));
}

// ---------------------------------------------------------------------------
// Kernel A: blocks 0..199: g = h @ W (W via L1, hT in 10KB smem),
//           s_i/s_j fused from live accumulators.
//           blocks 200..207: c3[d][h] = sum_q W_e[d,h*16+q]*a3[q].
// ---------------------------------------------------------------------------
__global__ void __launch_bounds__(256) gemm_fused(const float* __restrict__ h,
                                                  const float* __restrict__ W,
                                                  const float* __restrict__ We,
                                                  const float* __restrict__ a)
{
    __shared__ float hT[Dd * HS];
    __shared__ float ash[48];

    int t = threadIdx.x;

    if (blockIdx.x >= 200) {             // ---- c3 path (one head per block)
        int hd = blockIdx.x - 200;
        __shared__ float a3sh[16];
        if (t < 16) a3sh[t] = a[32 + t];
        __syncthreads();
        if (t < Dd) {
            const float4* row = (const float4*)(We + (size_t)t * Dd + hd * 16);
            float s = 0.f;
            #pragma unroll
            for (int qv = 0; qv < 4; qv++) {
                float4 w4 = row[qv];
                s += w4.x * a3sh[qv * 4 + 0] + w4.y * a3sh[qv * 4 + 1]
                   + w4.z * a3sh[qv * 4 + 2] + w4.w * a3sh[qv * 4 + 3];
            }
            c3g[t * Hh + hd] = s;
        }
        return;
    }

    int row0 = blockIdx.x * RPB;
    if (t < 32) ash[t] = a[t];

    #pragma unroll 2
    for (int idx = t; idx < RPB * Dd; idx += 256) {
        int r = idx >> 7, k = idx & 127;
        hT[k * HS + r] = h[(size_t)(row0 + r) * Dd + k];
    }
    __syncthreads();

    int cvec = t & 31;
    int c0   = cvec * 4;
    int r0   = (t >> 5) * 2;
    float acc0[4] = {0.f, 0.f, 0.f, 0.f};
    float acc1[4] = {0.f, 0.f, 0.f, 0.f};

    const float4* Wv = (const float4*)W;
    #pragma unroll 8
    for (int k = 0; k < Dd; k++) {
        float4 w4 = Wv[k * 32 + cvec];
        float2 h2 = *(const float2*)&hT[k * HS + r0];
        acc0[0] += h2.x * w4.x;  acc0[1] += h2.x * w4.y;
        acc0[2] += h2.x * w4.z;  acc0[3] += h2.x * w4.w;
        acc1[0] += h2.y * w4.x;  acc1[1] += h2.y * w4.y;
        acc1[2] += h2.y * w4.z;  acc1[3] += h2.y * w4.w;
    }
    *(float4*)&g_buf[(size_t)(row0 + r0)     * Dd + c0] =
        make_float4(acc0[0], acc0[1], acc0[2], acc0[3]);
    *(float4*)&g_buf[(size_t)(row0 + r0 + 1) * Dd + c0] =
        make_float4(acc1[0], acc1[1], acc1[2], acc1[3]);

    {   // fused s_i / s_j
        int head = c0 >> 4;
        int qb   = c0 & 15;
        const float* a1 = ash;
        const float* a2 = ash + 16;
        float pi0 = acc0[0]*a1[qb] + acc0[1]*a1[qb+1] + acc0[2]*a1[qb+2] + acc0[3]*a1[qb+3];
        float pj0 = acc0[0]*a2[qb] + acc0[1]*a2[qb+1] + acc0[2]*a2[qb+2] + acc0[3]*a2[qb+3];
        float pi1 = acc1[0]*a1[qb] + acc1[1]*a1[qb+1] + acc1[2]*a1[qb+2] + acc1[3]*a1[qb+3];
        float pj1 = acc1[0]*a2[qb] + acc1[1]*a2[qb+1] + acc1[2]*a2[qb+2] + acc1[3]*a2[qb+3];
        pi0 += __shfl_xor_sync(0xffffffffu, pi0, 1);
        pi0 += __shfl_xor_sync(0xffffffffu, pi0, 2);
        pj0 += __shfl_xor_sync(0xffffffffu, pj0, 1);
        pj0 += __shfl_xor_sync(0xffffffffu, pj0, 2);
        pi1 += __shfl_xor_sync(0xffffffffu, pi1, 1);
        pi1 += __shfl_xor_sync(0xffffffffu, pi1, 2);
        pj1 += __shfl_xor_sync(0xffffffffu, pj1, 1);
        pj1 += __shfl_xor_sync(0xffffffffu, pj1, 2);
        if ((t & 3) == 0) {
            si_buf[(row0 + r0)     * Hh + head] = pi0;
            sj_buf[(row0 + r0)     * Hh + head] = pj0;
            si_buf[(row0 + r0 + 1) * Hh + head] = pi1;
            sj_buf[(row0 + r0 + 1) * Hh + head] = pj1;
        }
    }
}

// ---------------------------------------------------------------------------
// Kernel B: per (b,i). Stage 1: s_e = dis_tile @ c3 on tensor cores (3xTF32),
// DOUBLE-BUFFERED per-warp cp.async tiles (fill ti+1 overlaps compute ti).
// Stage 2 softmax. Stage 3 direct-LDG attn @ g.
// ---------------------------------------------------------------------------
__global__ void __launch_bounds__(256, 4) attn_kernel(const float* __restrict__ dis,
                                                      const int*   __restrict__ adj,
                                                      float*       __restrict__ out)
{
    extern __shared__ __align__(16) float dsm[];
    float*    bufs   = dsm + SM_BUFS;
    float*    esh2   = dsm + SM_ESH;
    float*    sjsh   = dsm + SM_SJ;
    uint32_t* c3hi_s = (uint32_t*)(dsm + SM_C3HI);
    uint32_t* c3lo_s = (uint32_t*)(dsm + SM_C3LO);
    int*      adjsh  = (int*)(dsm + SM_ADJ);
    float*    si_sh  = dsm + SM_SI;
    float*    inv_sh = dsm + SM_INV;

    int tid  = threadIdx.x;
    int lane = tid & 31;
    int warp = tid >> 5;                 // 0..7
    int row  = blockIdx.x;               // b*200 + i
    int b    = row / Nn;
    size_t rb = (size_t)row * Nn;

    // Prologue loads
    for (int idx = tid; idx < Nn * Hh; idx += 256)
        sjsh[idx] = sj_buf[(size_t)b * Nn * Hh + idx];
    for (int idx = tid; idx < Nn; idx += 256)
        adjsh[idx] = adj[rb + idx];
    if (tid < Hh) si_sh[tid] = si_buf[row * Hh + tid];
    for (int idx = tid; idx < Dd * Hh; idx += 256) {
        float v = c3g[idx];
        uint32_t hi = f2tf32(v);
        c3hi_s[idx] = hi;
        c3lo_s[idx] = f2tf32(v - __uint_as_float(hi));
    }
    __syncthreads();

    // Per-warp double buffer: 2 slots x 2KB.
    uint32_t buf_sa = (uint32_t)__cvta_generic_to_shared(bufs) + warp * 4096;
    int g4 = lane >> 2;                  // groupID
    int t4 = lane & 3;                   // threadID-in-group

    // Lane-invariant fill geometry: it-th cp covers rows it*4+lr, col u*4.
    int lr = lane >> 3;                  // 0..3
    int u  = lane & 7;                   // 0..7
    uint32_t soff[4];
    #pragma unroll
    for (int it = 0; it < 4; it++) {
        int r = it * 4 + lr;
        soff[it] = (uint32_t)((r * 8 + (u ^ (r & 7))) * 16);
    }
    // ldmatrix geometry (lane-invariant parts)
    int mi = lane >> 3, ri = lane & 7;
    int rr = ri + 8 * (mi & 1);
    int mh = mi >> 1;
    uint32_t rr8 = (uint32_t)(rr * 8);

    // ---- Stage 1: chunks of 16 j-rows; warp w owns chunks {w, w+8} (<13).
    {
        int nc = (warp < 5) ? 2 : 1;
        int T  = nc * 4;                 // tiles: ti = ci*4 + kb

        // issue tile ti into slot
        auto issue = [&](int ti, int slot) {
            int ci = ti >> 2, kb = ti & 3;
            int j0 = (warp + ci * 8) * 16;
            uint32_t sb = buf_sa + (uint32_t)slot * 2048;
            #pragma unroll
            for (int it = 0; it < 4; it++) {
                int j = j0 + it * 4 + lr;
                if (j > 199) j = 199;
                cp_async16(sb + soff[it],
                           dis + (rb + j) * (size_t)Dd + kb * 32 + u * 4);
            }
        };

        float d0 = 0.f, d1 = 0.f, d2 = 0.f, d3 = 0.f;
        issue(0, 0);
        CP_COMMIT();
        for (int ti = 0; ti < T; ti++) {
            if (ti + 1 < T) issue(ti + 1, (ti + 1) & 1);
            CP_COMMIT();
            CP_WAIT1();
            __syncwarp();

            uint32_t abase = buf_sa + (uint32_t)(ti & 1) * 2048;
            int kb = ti & 3;
            #pragma unroll
            for (int s = 0; s < 4; s++) {
                int uu = 2 * s + mh;
                uint32_t a0, a1, a2, a3;
                ldm4(a0, a1, a2, a3, abase + (rr8 + (uint32_t)(uu ^ ri)) * 16);

                uint32_t ah0 = f2tf32(__uint_as_float(a0));
                uint32_t ah1 = f2tf32(__uint_as_float(a1));
                uint32_t ah2 = f2tf32(__uint_as_float(a2));
                uint32_t ah3 = f2tf32(__uint_as_float(a3));
                uint32_t al0 = f2tf32(__uint_as_float(a0) - __uint_as_float(ah0));
                uint32_t al1 = f2tf32(__uint_as_float(a1) - __uint_as_float(ah1));
                uint32_t al2 = f2tf32(__uint_as_float(a2) - __uint_as_float(ah2));
                uint32_t al3 = f2tf32(__uint_as_float(a3) - __uint_as_float(ah3));

                int kB = kb * 32 + s * 8 + t4;
                uint32_t bh0 = c3hi_s[kB * Hh + g4];
                uint32_t bh1 = c3hi_s[(kB + 4) * Hh + g4];
                uint32_t bl0 = c3lo_s[kB * Hh + g4];
                uint32_t bl1 = c3lo_s[(kB + 4) * Hh + g4];

                mma_tf32(d0, d1, d2, d3, ah0, ah1, ah2, ah3, bh0, bh1);
                mma_tf32(d0, d1, d2, d3, al0, al1, al2, al3, bh0, bh1);
                mma_tf32(d0, d1, d2, d3, ah0, ah1, ah2, ah3, bl0, bl1);
            }

            if (kb == 3) {   // epilogue for chunk ci = ti>>2
                int j0 = (warp + (ti >> 2) * 8) * 16;
                int h0 = 2 * t4, h1 = h0 + 1;
                int jA = j0 + g4;
                if (jA < 200) {
                    float e0 = d0 + si_sh[h0] + sjsh[jA * Hh + h0];
                    float e1 = d1 + si_sh[h1] + sjsh[jA * Hh + h1];
                    e0 = (e0 > 0.f) ? e0 : NEG_SLOPE * e0;
                    e1 = (e1 > 0.f) ? e1 : NEG_SLOPE * e1;
                    if (adjsh[jA] == 0) { e0 = -INFINITY; e1 = -INFINITY; }
                    esh2[jA * ES9 + h0] = e0;
                    esh2[jA * ES9 + h1] = e1;
                }
                int jB = j0 + 8 + g4;
                if (jB < 200) {
                    float e2 = d2 + si_sh[h0] + sjsh[jB * Hh + h0];
                    float e3 = d3 + si_sh[h1] + sjsh[jB * Hh + h1];
                    e2 = (e2 > 0.f) ? e2 : NEG_SLOPE * e2;
                    e3 = (e3 > 0.f) ? e3 : NEG_SLOPE * e3;
                    if (adjsh[jB] == 0) { e2 = -INFINITY; e3 = -INFINITY; }
                    esh2[jB * ES9 + h0] = e2;
                    esh2[jB * ES9 + h1] = e3;
                }
                d0 = d1 = d2 = d3 = 0.f;
            }
        }
    }
    __syncthreads();

    // ---- Stage 2: softmax over j, one warp per head (stride-9: no conflicts).
    {
        int hh = warp;
        float m = -INFINITY;
        for (int j = lane; j < Nn; j += 32)
            m = fmaxf(m, esh2[j * ES9 + hh]);
        #pragma unroll
        for (int o = 16; o > 0; o >>= 1)
            m = fmaxf(m, __shfl_xor_sync(0xffffffffu, m, o));
        float s = 0.f;
        for (int j = lane; j < Nn; j += 32) {
            float p = __expf(esh2[j * ES9 + hh] - m);
            esh2[j * ES9 + hh] = p;
            s += p;
        }
        #pragma unroll
        for (int o = 16; o > 0; o >>= 1)
            s += __shfl_xor_sync(0xffffffffu, s, o);
        if (lane == 0) inv_sh[hh] = 1.f / s;
    }
    __syncthreads();

    // ---- Stage 3: out[d] = (1/s) * sum_j p[j][h(d)] * g[b,j,d]. Direct LDG.
    {
        const float4* gvec = (const float4*)g_buf;
        size_t gb = (size_t)b * Nn;
        int myh = lane >> 2;
        float ax = 0.f, ay = 0.f, az = 0.f, aw = 0.f;
        #pragma unroll 1
        for (int c = 0; c < 4; c++) {
            float4 gv[6]; float p[6];
            #pragma unroll
            for (int uu2 = 0; uu2 < 6; uu2++) {
                int jj = warp + 8 * (c * 6 + uu2);
                gv[uu2] = gvec[(gb + jj) * 32 + lane];
                p[uu2]  = esh2[jj * ES9 + myh];
            }
            #pragma unroll
            for (int uu2 = 0; uu2 < 6; uu2++) {
                ax += p[uu2] * gv[uu2].x;  ay += p[uu2] * gv[uu2].y;
                az += p[uu2] * gv[uu2].z;  aw += p[uu2] * gv[uu2].w;
            }
        }
        {
            int jj = warp + 192;
            float4 gv = gvec[(gb + jj) * 32 + lane];
            float  p  = esh2[jj * ES9 + myh];
            ax += p * gv.x;  ay += p * gv.y;  az += p * gv.z;  aw += p * gv.w;
        }
        float* part = sjsh;                     // alias (sjsh dead now)
        *(float4*)&part[warp * Dd + lane * 4] = make_float4(ax, ay, az, aw);
        __syncthreads();
        if (tid < Dd) {
            int d = tid;
            float s = 0.f;
            #pragma unroll
            for (int w = 0; w < Hh; w++) s += part[w * Dd + d];
            out[(size_t)row * Dd + d] = s * inv_sh[d >> 4];
        }
    }
}

// ---------------------------------------------------------------------------
extern "C" void kernel_launch(void* const* d_in, const int* in_sizes, int n_in,
                              void* d_out, int out_size)
{
    const float* h   = (const float*)d_in[0];
    const int*   adj = (const int*)  d_in[1];
    const float* dis = (const float*)d_in[2];
    const float* W   = (const float*)d_in[3];
    const float* We  = (const float*)d_in[4];
    const float* a   = (const float*)d_in[5];
    float* out = (float*)d_out;

    size_t smem = SM_TOTALF * sizeof(float);   // 55712 B
    cudaFuncSetAttribute(attn_kernel, cudaFuncAttributeMaxDynamicSharedMemorySize,
                         (int)smem);

    gemm_fused<<<208, 256>>>(h, W, We, a);
    attn_kernel<<<ROWS, 256, smem>>>(dis, adj, out);
}

// round 11
// speedup vs baseline: 1.8766x; 1.0208x over previous
#include <cuda_runtime.h>
#include <math.h>
#include <stdint.h>

#define Bb 16
#define Nn 200
#define Dd 128
#define Hh 8
#define ROWS (Bb*Nn)          // 3200
#define NEG_SLOPE 0.2f
#define RPB 16                // rows per gemm block
#define HS 20                 // hT row stride (floats)
#define ES9 9                 // esh2 row stride (conflict-free softmax)

// attn dynamic smem layout (floats)
#define SM_BUFS   0                       // 8 warps x 2 slots x 512 = 8192
#define SM_ESH    8192                    // 208*9 = 1872
#define SM_SJ     (SM_ESH + 1872)         // 1600
#define SM_C3PH   (SM_SJ + 1600)          // 512 uint2 = 1024 floats
#define SM_C3PL   (SM_C3PH + 1024)        // 1024
#define SM_ADJ    (SM_C3PL + 1024)        // 200
#define SM_SI     (SM_ADJ + 200)          // 8
#define SM_INV    (SM_SI + 8)             // 8
#define SM_TOTALF (SM_INV + 8)            // 13928 floats = 55712 B

// Scratch (static device globals — no allocation)
__device__ float g_buf[ROWS * Dd];      // g = h @ W           (1.6 MB)
__device__ float si_buf[ROWS * Hh];     // s_i
__device__ float sj_buf[ROWS * Hh];     // s_j
__device__ float c3g[Dd * Hh];          // W_e folded with a3   [d][h]

__device__ __forceinline__ void cp_async16(uint32_t smem_addr, const void* gptr) {
    asm volatile("cp.async.cg.shared.global [%0], [%1], 16;\n"
                 :: "r"(smem_addr), "l"(gptr));
}
#define CP_COMMIT()  asm volatile("cp.async.commit_group;\n" ::: "memory")
#define CP_WAIT1()   asm volatile("cp.async.wait_group 1;\n" ::: "memory")

__device__ __forceinline__ uint32_t f2tf32(float x) {
    uint32_t r; asm("cvt.rna.tf32.f32 %0, %1;" : "=r"(r) : "f"(x)); return r;
}
__device__ __forceinline__ void ldm4(uint32_t& r0, uint32_t& r1, uint32_t& r2,
                                     uint32_t& r3, uint32_t addr) {
    asm volatile("ldmatrix.sync.aligned.m8n8.x4.shared.b16 {%0,%1,%2,%3}, [%4];"
                 : "=r"(r0), "=r"(r1), "=r"(r2), "=r"(r3) : "r"(addr));
}
__device__ __forceinline__ void mma_tf32(float& d0, float& d1, float& d2, float& d3,
                                         uint32_t a0, uint32_t a1, uint32_t a2,
                                         uint32_t a3, uint32_t b0, uint32_t b1) {
    asm volatile("mma.sync.aligned.m16n8k8.row.col.f32.tf32.tf32.f32 "
                 "{%0,%1,%2,%3}, {%4,%5,%6,%7}, {%8,%9}, {%0,%1,%2,%3};"
                 : "+f"(d0), "+f"(d1), "+f"(d2), "+f"(d3)
                 : "r"(a0), "r"(a1), "r"(a2), "r"(a3), "r"(b0), "r"(b1));
}

// ---------------------------------------------------------------------------
// Kernel A: blocks 0..199: g = h @ W (W via L1, hT in 10KB smem),
//           s_i/s_j fused from live accumulators.
//           blocks 200..207: c3[d][h] = sum_q W_e[d,h*16+q]*a3[q].
// ---------------------------------------------------------------------------
__global__ void __launch_bounds__(256) gemm_fused(const float* __restrict__ h,
                                                  const float* __restrict__ W,
                                                  const float* __restrict__ We,
                                                  const float* __restrict__ a)
{
    __shared__ float hT[Dd * HS];
    __shared__ float ash[48];

    int t = threadIdx.x;

    if (blockIdx.x >= 200) {             // ---- c3 path (one head per block)
        int hd = blockIdx.x - 200;
        __shared__ float a3sh[16];
        if (t < 16) a3sh[t] = a[32 + t];
        __syncthreads();
        if (t < Dd) {
            const float4* row = (const float4*)(We + (size_t)t * Dd + hd * 16);
            float s = 0.f;
            #pragma unroll
            for (int qv = 0; qv < 4; qv++) {
                float4 w4 = row[qv];
                s += w4.x * a3sh[qv * 4 + 0] + w4.y * a3sh[qv * 4 + 1]
                   + w4.z * a3sh[qv * 4 + 2] + w4.w * a3sh[qv * 4 + 3];
            }
            c3g[t * Hh + hd] = s;
        }
        return;
    }

    int row0 = blockIdx.x * RPB;
    if (t < 32) ash[t] = a[t];

    #pragma unroll 2
    for (int idx = t; idx < RPB * Dd; idx += 256) {
        int r = idx >> 7, k = idx & 127;
        hT[k * HS + r] = h[(size_t)(row0 + r) * Dd + k];
    }
    __syncthreads();

    int cvec = t & 31;
    int c0   = cvec * 4;
    int r0   = (t >> 5) * 2;
    float acc0[4] = {0.f, 0.f, 0.f, 0.f};
    float acc1[4] = {0.f, 0.f, 0.f, 0.f};

    const float4* Wv = (const float4*)W;
    #pragma unroll 16
    for (int k = 0; k < Dd; k++) {
        float4 w4 = Wv[k * 32 + cvec];
        float2 h2 = *(const float2*)&hT[k * HS + r0];
        acc0[0] += h2.x * w4.x;  acc0[1] += h2.x * w4.y;
        acc0[2] += h2.x * w4.z;  acc0[3] += h2.x * w4.w;
        acc1[0] += h2.y * w4.x;  acc1[1] += h2.y * w4.y;
        acc1[2] += h2.y * w4.z;  acc1[3] += h2.y * w4.w;
    }
    *(float4*)&g_buf[(size_t)(row0 + r0)     * Dd + c0] =
        make_float4(acc0[0], acc0[1], acc0[2], acc0[3]);
    *(float4*)&g_buf[(size_t)(row0 + r0 + 1) * Dd + c0] =
        make_float4(acc1[0], acc1[1], acc1[2], acc1[3]);

    {   // fused s_i / s_j
        int head = c0 >> 4;
        int qb   = c0 & 15;
        const float* a1 = ash;
        const float* a2 = ash + 16;
        float pi0 = acc0[0]*a1[qb] + acc0[1]*a1[qb+1] + acc0[2]*a1[qb+2] + acc0[3]*a1[qb+3];
        float pj0 = acc0[0]*a2[qb] + acc0[1]*a2[qb+1] + acc0[2]*a2[qb+2] + acc0[3]*a2[qb+3];
        float pi1 = acc1[0]*a1[qb] + acc1[1]*a1[qb+1] + acc1[2]*a1[qb+2] + acc1[3]*a1[qb+3];
        float pj1 = acc1[0]*a2[qb] + acc1[1]*a2[qb+1] + acc1[2]*a2[qb+2] + acc1[3]*a2[qb+3];
        pi0 += __shfl_xor_sync(0xffffffffu, pi0, 1);
        pi0 += __shfl_xor_sync(0xffffffffu, pi0, 2);
        pj0 += __shfl_xor_sync(0xffffffffu, pj0, 1);
        pj0 += __shfl_xor_sync(0xffffffffu, pj0, 2);
        pi1 += __shfl_xor_sync(0xffffffffu, pi1, 1);
        pi1 += __shfl_xor_sync(0xffffffffu, pi1, 2);
        pj1 += __shfl_xor_sync(0xffffffffu, pj1, 1);
        pj1 += __shfl_xor_sync(0xffffffffu, pj1, 2);
        if ((t & 3) == 0) {
            si_buf[(row0 + r0)     * Hh + head] = pi0;
            sj_buf[(row0 + r0)     * Hh + head] = pj0;
            si_buf[(row0 + r0 + 1) * Hh + head] = pi1;
            sj_buf[(row0 + r0 + 1) * Hh + head] = pj1;
        }
    }
}

// ---------------------------------------------------------------------------
// Kernel B: per (b,i). Stage 1: s_e = dis_tile @ c3 on tensor cores (3xTF32,
// cheap split: rna hi + raw residual), double-buffered per-warp cp.async
// tiles, hoisted addressing, pair-packed B frags. Stage 2 softmax.
// Stage 3 direct-LDG attn @ g.
// ---------------------------------------------------------------------------
__global__ void __launch_bounds__(256, 4) attn_kernel(const float* __restrict__ dis,
                                                      const int*   __restrict__ adj,
                                                      float*       __restrict__ out)
{
    extern __shared__ __align__(16) float dsm[];
    float*    bufs   = dsm + SM_BUFS;
    float*    esh2   = dsm + SM_ESH;
    float*    sjsh   = dsm + SM_SJ;
    uint2*    c3ph   = (uint2*)(dsm + SM_C3PH);   // (hi[kB], hi[kB+4])
    uint2*    c3pl   = (uint2*)(dsm + SM_C3PL);   // (lo[kB], lo[kB+4])
    int*      adjsh  = (int*)(dsm + SM_ADJ);
    float*    si_sh  = dsm + SM_SI;
    float*    inv_sh = dsm + SM_INV;

    int tid  = threadIdx.x;
    int lane = tid & 31;
    int warp = tid >> 5;                 // 0..7
    int row  = blockIdx.x;               // b*200 + i
    int b    = row / Nn;
    size_t rb = (size_t)row * Nn;

    // Prologue loads
    for (int idx = tid; idx < Nn * Hh; idx += 256)
        sjsh[idx] = sj_buf[(size_t)b * Nn * Hh + idx];
    for (int idx = tid; idx < Nn; idx += 256)
        adjsh[idx] = adj[rb + idx];
    if (tid < Hh) si_sh[tid] = si_buf[row * Hh + tid];
    // Pack B fragments: idx = kb*128 + s*32 + t4*8 + g4.
    for (int idx = tid; idx < 512; idx += 256) {
        int g4i = idx & 7;
        int t4i = (idx >> 3) & 3;
        int si  = (idx >> 5) & 3;
        int kbi = idx >> 7;
        int kB  = kbi * 32 + si * 8 + t4i;
        float v0 = c3g[kB * Hh + g4i];
        float v1 = c3g[(kB + 4) * Hh + g4i];
        uint32_t h0 = f2tf32(v0), h1 = f2tf32(v1);
        c3ph[idx] = make_uint2(h0, h1);
        c3pl[idx] = make_uint2(f2tf32(v0 - __uint_as_float(h0)),
                               f2tf32(v1 - __uint_as_float(h1)));
    }
    __syncthreads();

    // Per-warp double buffer: 2 slots x 2KB.
    uint32_t buf_sa = (uint32_t)__cvta_generic_to_shared(bufs) + warp * 4096;
    int g4 = lane >> 2;                  // groupID
    int t4 = lane & 3;                   // threadID-in-group
    int laneoff = t4 * 8 + g4;           // B-frag lane offset

    // Lane-invariant fill geometry.
    int lr = lane >> 3;                  // 0..3
    int u  = lane & 7;                   // 0..7
    uint32_t soff[4];
    #pragma unroll
    for (int it = 0; it < 4; it++) {
        int r = it * 4 + lr;
        soff[it] = (uint32_t)((r * 8 + (u ^ (r & 7))) * 16);
    }
    // Hoisted global byte-offsets per (chunk, it), clamps included.
    uint32_t roff[2][4];
    #pragma unroll
    for (int ci = 0; ci < 2; ci++)
        #pragma unroll
        for (int it = 0; it < 4; it++) {
            int j = (warp + ci * 8) * 16 + it * 4 + lr;
            if (j > 199) j = 199;
            roff[ci][it] = (uint32_t)(rb + j) * (Dd * 4) + (uint32_t)u * 16;
        }
    // ldmatrix geometry.
    int mi = lane >> 3, ri = lane & 7;
    int rr = ri + 8 * (mi & 1);
    int mh = mi >> 1;
    uint32_t rr8 = (uint32_t)(rr * 8);

    // ---- Stage 1: chunks of 16 j-rows; warp w owns chunks {w, w+8} (<13).
    {
        int nc = (warp < 5) ? 2 : 1;
        int T  = nc * 4;                 // tiles: ti = ci*4 + kb

        auto issue = [&](int ti, int slot) {
            int ci = ti >> 2, kb = ti & 3;
            uint32_t sb = buf_sa + (uint32_t)slot * 2048;
            const char* dbase = (const char*)dis + (kb << 7);
            #pragma unroll
            for (int it = 0; it < 4; it++)
                cp_async16(sb + soff[it], dbase + roff[ci][it]);
        };

        float d0 = 0.f, d1 = 0.f, d2 = 0.f, d3 = 0.f;
        issue(0, 0);
        CP_COMMIT();
        for (int ti = 0; ti < T; ti++) {
            if (ti + 1 < T) issue(ti + 1, (ti + 1) & 1);
            CP_COMMIT();
            CP_WAIT1();
            __syncwarp();

            uint32_t abase = buf_sa + (uint32_t)(ti & 1) * 2048;
            int kb = ti & 3;
            #pragma unroll
            for (int s = 0; s < 4; s++) {
                int uu = 2 * s + mh;
                uint32_t a0, a1, a2, a3;
                ldm4(a0, a1, a2, a3, abase + (rr8 + (uint32_t)(uu ^ ri)) * 16);

                // Cheap 3xTF32 split: rna hi; residual fed raw (HW truncates).
                float f0 = __uint_as_float(a0), f1 = __uint_as_float(a1);
                float f2 = __uint_as_float(a2), f3 = __uint_as_float(a3);
                uint32_t ah0 = f2tf32(f0), ah1 = f2tf32(f1);
                uint32_t ah2 = f2tf32(f2), ah3 = f2tf32(f3);
                uint32_t al0 = __float_as_uint(f0 - __uint_as_float(ah0));
                uint32_t al1 = __float_as_uint(f1 - __uint_as_float(ah1));
                uint32_t al2 = __float_as_uint(f2 - __uint_as_float(ah2));
                uint32_t al3 = __float_as_uint(f3 - __uint_as_float(ah3));

                uint2 bh = c3ph[kb * 128 + s * 32 + laneoff];
                uint2 bl = c3pl[kb * 128 + s * 32 + laneoff];

                mma_tf32(d0, d1, d2, d3, ah0, ah1, ah2, ah3, bh.x, bh.y);
                mma_tf32(d0, d1, d2, d3, al0, al1, al2, al3, bh.x, bh.y);
                mma_tf32(d0, d1, d2, d3, ah0, ah1, ah2, ah3, bl.x, bl.y);
            }

            if (kb == 3) {   // epilogue for chunk ci = ti>>2
                int j0 = (warp + (ti >> 2) * 8) * 16;
                int h0 = 2 * t4, h1 = h0 + 1;
                int jA = j0 + g4;
                if (jA < 200) {
                    float e0 = d0 + si_sh[h0] + sjsh[jA * Hh + h0];
                    float e1 = d1 + si_sh[h1] + sjsh[jA * Hh + h1];
                    e0 = (e0 > 0.f) ? e0 : NEG_SLOPE * e0;
                    e1 = (e1 > 0.f) ? e1 : NEG_SLOPE * e1;
                    if (adjsh[jA] == 0) { e0 = -INFINITY; e1 = -INFINITY; }
                    esh2[jA * ES9 + h0] = e0;
                    esh2[jA * ES9 + h1] = e1;
                }
                int jB = j0 + 8 + g4;
                if (jB < 200) {
                    float e2 = d2 + si_sh[h0] + sjsh[jB * Hh + h0];
                    float e3 = d3 + si_sh[h1] + sjsh[jB * Hh + h1];
                    e2 = (e2 > 0.f) ? e2 : NEG_SLOPE * e2;
                    e3 = (e3 > 0.f) ? e3 : NEG_SLOPE * e3;
                    if (adjsh[jB] == 0) { e2 = -INFINITY; e3 = -INFINITY; }
                    esh2[jB * ES9 + h0] = e2;
                    esh2[jB * ES9 + h1] = e3;
                }
                d0 = d1 = d2 = d3 = 0.f;
            }
        }
    }
    __syncthreads();

    // ---- Stage 2: softmax over j, one warp per head (stride-9: no conflicts).
    {
        int hh = warp;
        float m = -INFINITY;
        for (int j = lane; j < Nn; j += 32)
            m = fmaxf(m, esh2[j * ES9 + hh]);
        #pragma unroll
        for (int o = 16; o > 0; o >>= 1)
            m = fmaxf(m, __shfl_xor_sync(0xffffffffu, m, o));
        float s = 0.f;
        for (int j = lane; j < Nn; j += 32) {
            float p = __expf(esh2[j * ES9 + hh] - m);
            esh2[j * ES9 + hh] = p;
            s += p;
        }
        #pragma unroll
        for (int o = 16; o > 0; o >>= 1)
            s += __shfl_xor_sync(0xffffffffu, s, o);
        if (lane == 0) inv_sh[hh] = 1.f / s;
    }
    __syncthreads();

    // ---- Stage 3: out[d] = (1/s) * sum_j p[j][h(d)] * g[b,j,d]. Direct LDG.
    {
        const float4* gvec = (const float4*)g_buf;
        size_t gb = (size_t)b * Nn;
        int myh = lane >> 2;
        float ax = 0.f, ay = 0.f, az = 0.f, aw = 0.f;
        #pragma unroll 1
        for (int c = 0; c < 4; c++) {
            float4 gv[6]; float p[6];
            #pragma unroll
            for (int uu2 = 0; uu2 < 6; uu2++) {
                int jj = warp + 8 * (c * 6 + uu2);
                gv[uu2] = gvec[(gb + jj) * 32 + lane];
                p[uu2]  = esh2[jj * ES9 + myh];
            }
            #pragma unroll
            for (int uu2 = 0; uu2 < 6; uu2++) {
                ax += p[uu2] * gv[uu2].x;  ay += p[uu2] * gv[uu2].y;
                az += p[uu2] * gv[uu2].z;  aw += p[uu2] * gv[uu2].w;
            }
        }
        {
            int jj = warp + 192;
            float4 gv = gvec[(gb + jj) * 32 + lane];
            float  p  = esh2[jj * ES9 + myh];
            ax += p * gv.x;  ay += p * gv.y;  az += p * gv.z;  aw += p * gv.w;
        }
        float* part = sjsh;                     // alias (sjsh dead now)
        *(float4*)&part[warp * Dd + lane * 4] = make_float4(ax, ay, az, aw);
        __syncthreads();
        if (tid < Dd) {
            int d = tid;
            float s = 0.f;
            #pragma unroll
            for (int w = 0; w < Hh; w++) s += part[w * Dd + d];
            out[(size_t)row * Dd + d] = s * inv_sh[d >> 4];
        }
    }
}

// ---------------------------------------------------------------------------
extern "C" void kernel_launch(void* const* d_in, const int* in_sizes, int n_in,
                              void* d_out, int out_size)
{
    const float* h   = (const float*)d_in[0];
    const int*   adj = (const int*)  d_in[1];
    const float* dis = (const float*)d_in[2];
    const float* W   = (const float*)d_in[3];
    const float* We  = (const float*)d_in[4];
    const float* a   = (const float*)d_in[5];
    float* out = (float*)d_out;

    size_t smem = SM_TOTALF * sizeof(float);   // 55712 B
    cudaFuncSetAttribute(attn_kernel, cudaFuncAttributeMaxDynamicSharedMemorySize,
                         (int)smem);

    gemm_fused<<<208, 256>>>(h, W, We, a);
    attn_kernel<<<ROWS, 256, smem>>>(dis, adj, out);
}